// round 1
// baseline (speedup 1.0000x reference)
#include <cuda_runtime.h>
#include <math.h>

#define BATCH 64
#define NTOK  1024
#define DIM   256
#define NSLOT 8
#define HID   512
#define NITER 3
#define JT    8
#define ROWS  (BATCH*NSLOT)   /* 512 */

// ---------------- scratch (device globals; no allocations allowed) ----------
__device__ float g_xn[BATCH*NTOK*DIM];     // LN(inputs)            64 MB
__device__ float g_slots[ROWS*DIM];
__device__ float g_sln[ROWS*DIM];          // LN_ff(slots) for MLP
__device__ float g_qw[ROWS*DIM];           // qW = LN_slots(slots) @ Wqk
__device__ float g_wqk[DIM*DIM];           // Wq^T @ Wk
__device__ float g_wuv[3*DIM*DIM];         // gru_wih @ Wv   [768,256]
__device__ float g_upd[ROWS*DIM];          // U' = (attn@xn)/rowsum
__device__ float g_gi[ROWS*3*DIM];
__device__ float g_gh[ROWS*3*DIM];
__device__ float g_h1[ROWS*HID];
__device__ float g_ypart[BATCH*JT*NSLOT*DIM];
__device__ float g_rspart[BATCH*JT*NSLOT];

__device__ __forceinline__ float warp_sum(float v) {
    v += __shfl_xor_sync(0xffffffffu, v, 16);
    v += __shfl_xor_sync(0xffffffffu, v, 8);
    v += __shfl_xor_sync(0xffffffffu, v, 4);
    v += __shfl_xor_sync(0xffffffffu, v, 2);
    v += __shfl_xor_sync(0xffffffffu, v, 1);
    return v;
}

// ---------------- init: slots = mu + noise * exp(sigma) ---------------------
__global__ void slots_init_kernel(const float* __restrict__ noise,
                                  const float* __restrict__ mu,
                                  const float* __restrict__ sigma) {
    int i = blockIdx.x * 256 + threadIdx.x;
    int d = i & 255;
    g_slots[i] = mu[d] + noise[i] * expf(sigma[d]);
}

// ---------------- W_qk[f,d] = sum_e Wq[e,f] * Wk[e,d] -----------------------
__global__ void wqk_kernel(const float* __restrict__ Wq, const float* __restrict__ Wk) {
    int f0 = blockIdx.x * 8, d = threadIdx.x;
    float acc[8] = {};
    for (int e = 0; e < DIM; e++) {
        float wk = Wk[e*DIM + d];
#pragma unroll
        for (int u = 0; u < 8; u++) acc[u] += Wq[e*DIM + f0 + u] * wk;
    }
#pragma unroll
    for (int u = 0; u < 8; u++) g_wqk[(f0+u)*DIM + d] = acc[u];
}

// ---------------- W_uv[g,e] = sum_d wih[g,d] * Wv[d,e] ----------------------
__global__ void wuv_kernel(const float* __restrict__ wih, const float* __restrict__ Wv) {
    int g0 = blockIdx.x * 8, e = threadIdx.x;
    float acc[8] = {};
    for (int d = 0; d < DIM; d++) {
        float v = Wv[d*DIM + e];
#pragma unroll
        for (int u = 0; u < 8; u++) acc[u] += wih[(g0+u)*DIM + d] * v;
    }
#pragma unroll
    for (int u = 0; u < 8; u++) g_wuv[(g0+u)*DIM + e] = acc[u];
}

// ---------------- LN(inputs) -> g_xn  (1 warp per row) ----------------------
__global__ void __launch_bounds__(256) ln_in_kernel(const float* __restrict__ in,
                                                    const float* __restrict__ w,
                                                    const float* __restrict__ b) {
    int row  = blockIdx.x * 8 + (threadIdx.x >> 5);
    int lane = threadIdx.x & 31;
    const float4* ip = (const float4*)(in + (size_t)row * DIM);
    float4 v0 = ip[lane*2], v1 = ip[lane*2+1];
    float s  = v0.x+v0.y+v0.z+v0.w + v1.x+v1.y+v1.z+v1.w;
    float sq = v0.x*v0.x+v0.y*v0.y+v0.z*v0.z+v0.w*v0.w
             + v1.x*v1.x+v1.y*v1.y+v1.z*v1.z+v1.w*v1.w;
    s = warp_sum(s); sq = warp_sum(sq);
    float mu  = s * (1.f/256.f);
    float var = sq * (1.f/256.f) - mu*mu;
    float rstd = rsqrtf(fmaxf(var, 0.f) + 1e-5f);
    const float4* wp = (const float4*)w; const float4* bp = (const float4*)b;
    float4 w0 = wp[lane*2], w1 = wp[lane*2+1];
    float4 b0 = bp[lane*2], b1 = bp[lane*2+1];
    float4 o0, o1;
    o0.x=(v0.x-mu)*rstd*w0.x+b0.x; o0.y=(v0.y-mu)*rstd*w0.y+b0.y;
    o0.z=(v0.z-mu)*rstd*w0.z+b0.z; o0.w=(v0.w-mu)*rstd*w0.w+b0.w;
    o1.x=(v1.x-mu)*rstd*w1.x+b1.x; o1.y=(v1.y-mu)*rstd*w1.y+b1.y;
    o1.z=(v1.z-mu)*rstd*w1.z+b1.z; o1.w=(v1.w-mu)*rstd*w1.w+b1.w;
    float4* op = (float4*)(g_xn + (size_t)row * DIM);
    op[lane*2] = o0; op[lane*2+1] = o1;
}

// -------- s = LN_slots(slots); qW = s @ W_qk   (1 block per batch) ----------
__global__ void __launch_bounds__(256) slots_qw_kernel(const float* __restrict__ lw,
                                                       const float* __restrict__ lb) {
    int b = blockIdx.x, tid = threadIdx.x, lane = tid & 31, w = tid >> 5;
    __shared__ float sln[NSLOT*DIM];
    {
        const float4* sp = (const float4*)(g_slots + (size_t)(b*8 + w) * DIM);
        float4 v0 = sp[lane*2], v1 = sp[lane*2+1];
        float s  = v0.x+v0.y+v0.z+v0.w + v1.x+v1.y+v1.z+v1.w;
        float sq = v0.x*v0.x+v0.y*v0.y+v0.z*v0.z+v0.w*v0.w
                 + v1.x*v1.x+v1.y*v1.y+v1.z*v1.z+v1.w*v1.w;
        s = warp_sum(s); sq = warp_sum(sq);
        float mu  = s * (1.f/256.f);
        float var = sq * (1.f/256.f) - mu*mu;
        float rstd = rsqrtf(fmaxf(var, 0.f) + 1e-5f);
        const float4* wp = (const float4*)lw; const float4* bp = (const float4*)lb;
        float4 w0 = wp[lane*2], w1 = wp[lane*2+1];
        float4 b0 = bp[lane*2], b1 = bp[lane*2+1];
        float4 o0, o1;
        o0.x=(v0.x-mu)*rstd*w0.x+b0.x; o0.y=(v0.y-mu)*rstd*w0.y+b0.y;
        o0.z=(v0.z-mu)*rstd*w0.z+b0.z; o0.w=(v0.w-mu)*rstd*w0.w+b0.w;
        o1.x=(v1.x-mu)*rstd*w1.x+b1.x; o1.y=(v1.y-mu)*rstd*w1.y+b1.y;
        o1.z=(v1.z-mu)*rstd*w1.z+b1.z; o1.w=(v1.w-mu)*rstd*w1.w+b1.w;
        float4* op = (float4*)&sln[w*DIM];
        op[lane*2] = o0; op[lane*2+1] = o1;
    }
    __syncthreads();
    float acc[8] = {};
    for (int f = 0; f < DIM; f += 4) {
        float q0 = g_wqk[(f+0)*DIM + tid];
        float q1 = g_wqk[(f+1)*DIM + tid];
        float q2 = g_wqk[(f+2)*DIM + tid];
        float q3 = g_wqk[(f+3)*DIM + tid];
#pragma unroll
        for (int r = 0; r < 8; r++) {
            float4 sv = *(const float4*)&sln[r*DIM + f];
            acc[r] += sv.x*q0 + sv.y*q1 + sv.z*q2 + sv.w*q3;
        }
    }
#pragma unroll
    for (int r = 0; r < 8; r++) g_qw[(size_t)(b*8+r)*DIM + tid] = acc[r];
}

// -------- fused attention: dots, softmax(slots axis), attn out, Y partials --
__global__ void __launch_bounds__(256, 1) attn_kernel(float* __restrict__ attn_out, int it) {
    int jt = blockIdx.x, b = blockIdx.y;
    int tid = threadIdx.x, lane = tid & 31, w = tid >> 5;
    __shared__ float ysm[NSLOT*DIM];
    __shared__ float rssm[NSLOT];
#pragma unroll
    for (int u = 0; u < 8; u++) ysm[tid + 256*u] = 0.f;
    if (tid < 8) rssm[tid] = 0.f;

    const float scale = 0.0625f;  // 256^-0.5
    float qr[8][8];
#pragma unroll
    for (int i = 0; i < 8; i++)
#pragma unroll
        for (int k = 0; k < 8; k++)
            qr[i][k] = g_qw[(size_t)(b*8+i)*DIM + lane + 32*k] * scale;

    float yacc[8][8] = {};
    float rs = 0.f;
    __syncthreads();

    for (int c = 0; c < 16; c++) {
        int j = jt*128 + w + c*8;
        const float* xp = g_xn + ((size_t)b*NTOK + j) * DIM;
        float xv[8];
#pragma unroll
        for (int k = 0; k < 8; k++) xv[k] = xp[lane + 32*k];

        float s[8] = {};
#pragma unroll
        for (int i = 0; i < 8; i++)
#pragma unroll
            for (int k = 0; k < 8; k++) s[i] += qr[i][k] * xv[k];
#pragma unroll
        for (int i = 0; i < 8; i++) s[i] = warp_sum(s[i]);

        float m = s[0];
#pragma unroll
        for (int i = 1; i < 8; i++) m = fmaxf(m, s[i]);
        float a[8]; float asum = 0.f;
#pragma unroll
        for (int i = 0; i < 8; i++) { a[i] = expf(s[i] - m); asum += a[i]; }
        float inv = 1.f / asum;
#pragma unroll
        for (int i = 0; i < 8; i++) a[i] = a[i] * inv + 1e-8f;

        float* ap = attn_out + (size_t)((b*NITER + it)*NSLOT) * NTOK + j;
#pragma unroll
        for (int i = 0; i < 8; i++)
            if (lane == i) { ap[i*NTOK] = a[i]; rs += a[i]; }

#pragma unroll
        for (int i = 0; i < 8; i++)
#pragma unroll
            for (int k = 0; k < 8; k++) yacc[i][k] += a[i] * xv[k];
    }

    for (int ww = 0; ww < 8; ww++) {   // barrier-serialized block reduction
        if (w == ww) {
#pragma unroll
            for (int i = 0; i < 8; i++)
#pragma unroll
                for (int k = 0; k < 8; k++)
                    ysm[i*DIM + lane + 32*k] += yacc[i][k];
            if (lane < 8) rssm[lane] += rs;
        }
        __syncthreads();
    }
    float* yp = g_ypart + (size_t)((b*JT + jt)*NSLOT) * DIM;
#pragma unroll
    for (int u = 0; u < 8; u++) yp[tid + 256*u] = ysm[tid + 256*u];
    if (tid < 8) g_rspart[(b*JT + jt)*NSLOT + tid] = rssm[tid];
}

// -------- reduce Y partials -> U' ------------------------------------------
__global__ void reduce_u_kernel() {
    int row = blockIdx.x, d = threadIdx.x;
    int b = row >> 3, i = row & 7;
    float y = 0.f, rsv = 0.f;
#pragma unroll
    for (int jt = 0; jt < JT; jt++) {
        y   += g_ypart[(size_t)((b*JT + jt)*NSLOT + i)*DIM + d];
        rsv += g_rspart[(b*JT + jt)*NSLOT + i];
    }
    g_upd[(size_t)row*DIM + d] = y / rsv;
}

// -------- generic C = A @ W^T (+bias) GEMM, 64x64x16 tiles ------------------
// mode bit0: relu, bit1: accumulate into existing C. blockIdx.z picks problem.
__global__ void __launch_bounds__(256) gemm_kernel(
    const float* __restrict__ A0, const float* __restrict__ W0,
    const float* __restrict__ bias0, float* __restrict__ C0,
    const float* __restrict__ A1, const float* __restrict__ W1,
    const float* __restrict__ bias1, float* __restrict__ C1,
    int M, int N, int K, int mode)
{
    const float* A = A0; const float* W = W0; const float* bias = bias0; float* C = C0;
    if (blockIdx.z) { A = A1; W = W1; bias = bias1; C = C1; }
    __shared__ float As[16][68];
    __shared__ float Bs[16][68];
    int tid = threadIdx.x;
    int m0 = blockIdx.y * 64, n0 = blockIdx.x * 64;
    int tx = tid & 15, ty = tid >> 4;
    int lr = tid >> 2, lk = (tid & 3) * 4;
    float acc[4][4] = {};
    for (int k0 = 0; k0 < K; k0 += 16) {
        float4 av = *(const float4*)&A[(size_t)(m0 + lr)*K + k0 + lk];
        float4 wv = *(const float4*)&W[(size_t)(n0 + lr)*K + k0 + lk];
        __syncthreads();
        As[lk+0][lr]=av.x; As[lk+1][lr]=av.y; As[lk+2][lr]=av.z; As[lk+3][lr]=av.w;
        Bs[lk+0][lr]=wv.x; Bs[lk+1][lr]=wv.y; Bs[lk+2][lr]=wv.z; Bs[lk+3][lr]=wv.w;
        __syncthreads();
#pragma unroll
        for (int kk = 0; kk < 16; kk++) {
            float4 a4 = *(const float4*)&As[kk][ty*4];
            float4 b4 = *(const float4*)&Bs[kk][tx*4];
            float a[4]  = {a4.x, a4.y, a4.z, a4.w};
            float bb[4] = {b4.x, b4.y, b4.z, b4.w};
#pragma unroll
            for (int i = 0; i < 4; i++)
#pragma unroll
                for (int j = 0; j < 4; j++) acc[i][j] += a[i] * bb[j];
        }
    }
    float bj[4];
#pragma unroll
    for (int j = 0; j < 4; j++) bj[j] = bias ? bias[n0 + tx*4 + j] : 0.f;
#pragma unroll
    for (int i = 0; i < 4; i++) {
        float* cp = C + (size_t)(m0 + ty*4 + i)*N + n0 + tx*4;
#pragma unroll
        for (int j = 0; j < 4; j++) {
            float v = acc[i][j] + bj[j];
            if (mode & 1) v = fmaxf(v, 0.f);
            if (mode & 2) v += cp[j];
            cp[j] = v;
        }
    }
}

// -------- GRU gates + LN_ff in one pass (1 block per slot row) --------------
__global__ void __launch_bounds__(256) gru_gates_ln_kernel(const float* __restrict__ lw,
                                                           const float* __restrict__ lb) {
    int row = blockIdx.x, d = threadIdx.x, lane = d & 31, w = d >> 5;
    const float* gi = g_gi + (size_t)row * 3*DIM;
    const float* gh = g_gh + (size_t)row * 3*DIM;
    float h = g_slots[(size_t)row*DIM + d];
    float r = 1.f / (1.f + expf(-(gi[d]       + gh[d])));
    float z = 1.f / (1.f + expf(-(gi[DIM+d]   + gh[DIM+d])));
    float n = tanhf(gi[2*DIM+d] + r * gh[2*DIM+d]);
    float s = (1.f - z) * n + z * h;
    g_slots[(size_t)row*DIM + d] = s;

    __shared__ float red[16];
    float ps = warp_sum(s), pq = warp_sum(s*s);
    if (lane == 0) { red[w] = ps; red[8+w] = pq; }
    __syncthreads();
    float tot = 0.f, totq = 0.f;
#pragma unroll
    for (int u = 0; u < 8; u++) { tot += red[u]; totq += red[8+u]; }
    float mu  = tot * (1.f/256.f);
    float var = totq * (1.f/256.f) - mu*mu;
    float rstd = rsqrtf(fmaxf(var, 0.f) + 1e-5f);
    g_sln[(size_t)row*DIM + d] = (s - mu) * rstd * lw[d] + lb[d];
}

__global__ void copy_slots_kernel(float* __restrict__ out) {
    int i = blockIdx.x * 256 + threadIdx.x;
    out[i] = g_slots[i];
}

// ---------------------------------------------------------------------------
extern "C" void kernel_launch(void* const* d_in, const int* in_sizes, int n_in,
                              void* d_out, int out_size) {
    const float* inputs  = (const float*)d_in[0];
    const float* noise   = (const float*)d_in[1];
    const float* mu      = (const float*)d_in[2];
    const float* sigma   = (const float*)d_in[3];
    const float* Wq      = (const float*)d_in[4];
    const float* Wk      = (const float*)d_in[5];
    const float* Wv      = (const float*)d_in[6];
    const float* wih     = (const float*)d_in[7];
    const float* whh     = (const float*)d_in[8];
    const float* bih     = (const float*)d_in[9];
    const float* bhh     = (const float*)d_in[10];
    const float* w1      = (const float*)d_in[11];
    const float* b1      = (const float*)d_in[12];
    const float* w2      = (const float*)d_in[13];
    const float* b2      = (const float*)d_in[14];
    const float* ln_in_w = (const float*)d_in[15];
    const float* ln_in_b = (const float*)d_in[16];
    const float* ln_s_w  = (const float*)d_in[17];
    const float* ln_s_b  = (const float*)d_in[18];
    const float* ln_ff_w = (const float*)d_in[19];
    const float* ln_ff_b = (const float*)d_in[20];

    float* out      = (float*)d_out;
    float* attn_out = out + BATCH*NSLOT*DIM;   // slots first, then attns [b,iter,slot,tok]

    float *p_upd, *p_wuv, *p_slots, *p_gi, *p_gh, *p_sln, *p_h1;
    cudaGetSymbolAddress((void**)&p_upd,   g_upd);
    cudaGetSymbolAddress((void**)&p_wuv,   g_wuv);
    cudaGetSymbolAddress((void**)&p_slots, g_slots);
    cudaGetSymbolAddress((void**)&p_gi,    g_gi);
    cudaGetSymbolAddress((void**)&p_gh,    g_gh);
    cudaGetSymbolAddress((void**)&p_sln,   g_sln);
    cudaGetSymbolAddress((void**)&p_h1,    g_h1);

    slots_init_kernel<<<ROWS, 256>>>(noise, mu, sigma);
    wqk_kernel<<<DIM/8, 256>>>(Wq, Wk);
    wuv_kernel<<<(3*DIM)/8, 256>>>(wih, Wv);
    ln_in_kernel<<<(BATCH*NTOK)/8, 256>>>(inputs, ln_in_w, ln_in_b);

    for (int it = 0; it < NITER; it++) {
        slots_qw_kernel<<<BATCH, 256>>>(ln_s_w, ln_s_b);
        attn_kernel<<<dim3(JT, BATCH), 256>>>(attn_out, it);
        reduce_u_kernel<<<ROWS, 256>>>();
        // gi = U' @ W_uv^T + bih ; gh = slots @ whh^T + bhh   (z picks problem)
        gemm_kernel<<<dim3((3*DIM)/64, ROWS/64, 2), 256>>>(
            p_upd, p_wuv, bih, p_gi,
            p_slots, whh, bhh, p_gh,
            ROWS, 3*DIM, DIM, 0);
        gru_gates_ln_kernel<<<ROWS, 256>>>(ln_ff_w, ln_ff_b);
        // h1 = relu(sln @ w1^T + b1)
        gemm_kernel<<<dim3(HID/64, ROWS/64, 1), 256>>>(
            p_sln, w1, b1, p_h1, p_sln, w1, b1, p_h1,
            ROWS, HID, DIM, 1);
        // slots += h1 @ w2^T + b2
        gemm_kernel<<<dim3(DIM/64, ROWS/64, 1), 256>>>(
            p_h1, w2, b2, p_slots, p_h1, w2, b2, p_slots,
            ROWS, DIM, HID, 2);
    }
    copy_slots_kernel<<<ROWS, 256>>>(out);
}

// round 4
// speedup vs baseline: 1.0421x; 1.0421x over previous
#include <cuda_runtime.h>
#include <math.h>

#define BATCH 64
#define NTOK  1024
#define DIM   256
#define NSLOT 8
#define HID   512
#define NITER 3
#define ROWS  (BATCH*NSLOT)   /* 512 */

// ---------------- scratch (device globals; no allocations allowed) ----------
__device__ float g_xn[BATCH*NTOK*DIM];     // LN(inputs)            64 MB
__device__ float g_slots[ROWS*DIM];
__device__ float g_sln[ROWS*DIM];          // LN_ff(slots) for MLP
__device__ float g_qw[ROWS*DIM];           // qW = LN_slots(slots) @ Wqk
__device__ float g_wqk[DIM*DIM];           // Wq^T @ Wk
__device__ float g_wuv[3*DIM*DIM];         // gru_wih @ Wv   [768,256]
__device__ float g_upd[ROWS*DIM];          // U' = (attn@xn)/rowsum
__device__ float g_gi[ROWS*3*DIM];
__device__ float g_gh[ROWS*3*DIM];
__device__ float g_h1[ROWS*HID];

__device__ __forceinline__ float warp_sum(float v) {
    v += __shfl_xor_sync(0xffffffffu, v, 16);
    v += __shfl_xor_sync(0xffffffffu, v, 8);
    v += __shfl_xor_sync(0xffffffffu, v, 4);
    v += __shfl_xor_sync(0xffffffffu, v, 2);
    v += __shfl_xor_sync(0xffffffffu, v, 1);
    return v;
}

// ---------------- init: slots = mu + noise * exp(sigma) ---------------------
__global__ void slots_init_kernel(const float* __restrict__ noise,
                                  const float* __restrict__ mu,
                                  const float* __restrict__ sigma) {
    int i = blockIdx.x * 256 + threadIdx.x;
    int d = i & 255;
    g_slots[i] = mu[d] + noise[i] * expf(sigma[d]);
}

// ---------------- W_qk[f,d] = sum_e Wq[e,f] * Wk[e,d] -----------------------
__global__ void wqk_kernel(const float* __restrict__ Wq, const float* __restrict__ Wk) {
    int f0 = blockIdx.x * 8, d = threadIdx.x;
    float acc[8] = {};
    for (int e = 0; e < DIM; e++) {
        float wk = Wk[e*DIM + d];
#pragma unroll
        for (int u = 0; u < 8; u++) acc[u] += Wq[e*DIM + f0 + u] * wk;
    }
#pragma unroll
    for (int u = 0; u < 8; u++) g_wqk[(f0+u)*DIM + d] = acc[u];
}

// ---------------- W_uv[g,e] = sum_d wih[g,d] * Wv[d,e] ----------------------
__global__ void wuv_kernel(const float* __restrict__ wih, const float* __restrict__ Wv) {
    int g0 = blockIdx.x * 8, e = threadIdx.x;
    float acc[8] = {};
    for (int d = 0; d < DIM; d++) {
        float v = Wv[d*DIM + e];
#pragma unroll
        for (int u = 0; u < 8; u++) acc[u] += wih[(g0+u)*DIM + d] * v;
    }
#pragma unroll
    for (int u = 0; u < 8; u++) g_wuv[(g0+u)*DIM + e] = acc[u];
}

// ---------------- LN(inputs) -> g_xn  (1 warp per row) ----------------------
__global__ void __launch_bounds__(256) ln_in_kernel(const float* __restrict__ in,
                                                    const float* __restrict__ w,
                                                    const float* __restrict__ b) {
    int row  = blockIdx.x * 8 + (threadIdx.x >> 5);
    int lane = threadIdx.x & 31;
    const float4* ip = (const float4*)(in + (size_t)row * DIM);
    float4 v0 = ip[lane*2], v1 = ip[lane*2+1];
    float s  = v0.x+v0.y+v0.z+v0.w + v1.x+v1.y+v1.z+v1.w;
    float sq = v0.x*v0.x+v0.y*v0.y+v0.z*v0.z+v0.w*v0.w
             + v1.x*v1.x+v1.y*v1.y+v1.z*v1.z+v1.w*v1.w;
    s = warp_sum(s); sq = warp_sum(sq);
    float mu  = s * (1.f/256.f);
    float var = sq * (1.f/256.f) - mu*mu;
    float rstd = rsqrtf(fmaxf(var, 0.f) + 1e-5f);
    const float4* wp = (const float4*)w; const float4* bp = (const float4*)b;
    float4 w0 = wp[lane*2], w1 = wp[lane*2+1];
    float4 b0 = bp[lane*2], b1 = bp[lane*2+1];
    float4 o0, o1;
    o0.x=(v0.x-mu)*rstd*w0.x+b0.x; o0.y=(v0.y-mu)*rstd*w0.y+b0.y;
    o0.z=(v0.z-mu)*rstd*w0.z+b0.z; o0.w=(v0.w-mu)*rstd*w0.w+b0.w;
    o1.x=(v1.x-mu)*rstd*w1.x+b1.x; o1.y=(v1.y-mu)*rstd*w1.y+b1.y;
    o1.z=(v1.z-mu)*rstd*w1.z+b1.z; o1.w=(v1.w-mu)*rstd*w1.w+b1.w;
    float4* op = (float4*)(g_xn + (size_t)row * DIM);
    op[lane*2] = o0; op[lane*2+1] = o1;
}

// -------- s = LN_slots(slots); qW = s @ W_qk   (1 block per batch) ----------
__global__ void __launch_bounds__(256) slots_qw_kernel(const float* __restrict__ lw,
                                                       const float* __restrict__ lb) {
    int b = blockIdx.x, tid = threadIdx.x, lane = tid & 31, w = tid >> 5;
    __shared__ float sln[NSLOT*DIM];
    {
        const float4* sp = (const float4*)(g_slots + (size_t)(b*8 + w) * DIM);
        float4 v0 = sp[lane*2], v1 = sp[lane*2+1];
        float s  = v0.x+v0.y+v0.z+v0.w + v1.x+v1.y+v1.z+v1.w;
        float sq = v0.x*v0.x+v0.y*v0.y+v0.z*v0.z+v0.w*v0.w
                 + v1.x*v1.x+v1.y*v1.y+v1.z*v1.z+v1.w*v1.w;
        s = warp_sum(s); sq = warp_sum(sq);
        float mu  = s * (1.f/256.f);
        float var = sq * (1.f/256.f) - mu*mu;
        float rstd = rsqrtf(fmaxf(var, 0.f) + 1e-5f);
        const float4* wp = (const float4*)lw; const float4* bp = (const float4*)lb;
        float4 w0 = wp[lane*2], w1 = wp[lane*2+1];
        float4 b0 = bp[lane*2], b1 = bp[lane*2+1];
        float4 o0, o1;
        o0.x=(v0.x-mu)*rstd*w0.x+b0.x; o0.y=(v0.y-mu)*rstd*w0.y+b0.y;
        o0.z=(v0.z-mu)*rstd*w0.z+b0.z; o0.w=(v0.w-mu)*rstd*w0.w+b0.w;
        o1.x=(v1.x-mu)*rstd*w1.x+b1.x; o1.y=(v1.y-mu)*rstd*w1.y+b1.y;
        o1.z=(v1.z-mu)*rstd*w1.z+b1.z; o1.w=(v1.w-mu)*rstd*w1.w+b1.w;
        float4* op = (float4*)&sln[w*DIM];
        op[lane*2] = o0; op[lane*2+1] = o1;
    }
    __syncthreads();
    float acc[8] = {};
    for (int f = 0; f < DIM; f += 4) {
        float q0 = g_wqk[(f+0)*DIM + tid];
        float q1 = g_wqk[(f+1)*DIM + tid];
        float q2 = g_wqk[(f+2)*DIM + tid];
        float q3 = g_wqk[(f+3)*DIM + tid];
#pragma unroll
        for (int r = 0; r < 8; r++) {
            float4 sv = *(const float4*)&sln[r*DIM + f];
            acc[r] += sv.x*q0 + sv.y*q1 + sv.z*q2 + sv.w*q3;
        }
    }
#pragma unroll
    for (int r = 0; r < 8; r++) g_qw[(size_t)(b*8+r)*DIM + tid] = acc[r];
}

// -------- pass 1: dots + softmax(slot axis) + attn write; thread = token ----
__global__ void __launch_bounds__(256) attn_dots_kernel(float* __restrict__ attn_out, int it) {
    int b = blockIdx.y, tile = blockIdx.x;
    int tid = threadIdx.x;
    int j = tile * 256 + tid;
    __shared__ float q_sm[NSLOT*DIM];   // 8KB, scaled q, broadcast reads
    for (int k = tid; k < NSLOT*DIM; k += 256)
        q_sm[k] = g_qw[(size_t)b*NSLOT*DIM + k] * 0.0625f;
    __syncthreads();

    const float4* xp = (const float4*)(g_xn + ((size_t)b*NTOK + j) * DIM);
    const float4* qp = (const float4*)q_sm;
    float s[8] = {};
#pragma unroll 4
    for (int d4 = 0; d4 < 64; d4++) {
        float4 x4 = xp[d4];
#pragma unroll
        for (int i = 0; i < 8; i++) {
            float4 q4 = qp[i*64 + d4];
            s[i] += x4.x*q4.x + x4.y*q4.y + x4.z*q4.z + x4.w*q4.w;
        }
    }
    float m = s[0];
#pragma unroll
    for (int i = 1; i < 8; i++) m = fmaxf(m, s[i]);
    float a[8], asum = 0.f;
#pragma unroll
    for (int i = 0; i < 8; i++) { a[i] = __expf(s[i] - m); asum += a[i]; }
    float inv = 1.f / asum;
    float* ap = attn_out + ((size_t)(b*NITER + it)*NSLOT)*NTOK + j;
#pragma unroll
    for (int i = 0; i < 8; i++) ap[i*NTOK] = a[i]*inv + 1e-8f;
}

// -------- pass 2: U' = (attn @ xn) / rowsum(attn)  -------------------------
// grid (2, BATCH): blockIdx.x = d-half (128 dims). warp = token-group (128 t),
// lane = d4-group. attn reads are uniform-address LDG.128 (L1/L2 broadcast);
// x reads coalesced LDG.128. smem = 32KB red + 32B rowsums (fits static limit).
__global__ void __launch_bounds__(256) attn_y_kernel(const float* __restrict__ attn_out, int it) {
    int b = blockIdx.y, half = blockIdx.x;
    int tid = threadIdx.x, lane = tid & 31, w = tid >> 5;
    __shared__ float red[8*NSLOT*128];        // 32KB: [tgroup][slot][d_local]
    __shared__ float rssm[NSLOT];

    const float* ab = attn_out + (size_t)(b*NITER + it)*NSLOT*NTOK;

    // per-slot rowsum: warp w sums slot w (coalesced gmem reads)
    {
        float rs = 0.f;
#pragma unroll
        for (int k = 0; k < 32; k++) rs += ab[w*NTOK + lane + 32*k];
        rs = warp_sum(rs);
        if (lane == 0) rssm[w] = rs;
    }

    // Y: warp w covers tokens [w*128, w*128+128), lane covers 4 dims
    int dd = half*128 + lane*4;
    const float* xb = g_xn + (size_t)b*NTOK*DIM;
    float acc[8][4] = {};
    int t0 = w * 128;
    for (int tt = 0; tt < 128; tt += 4) {
        int t = t0 + tt;
        float4 xv0 = *(const float4*)&xb[(size_t)(t+0)*DIM + dd];
        float4 xv1 = *(const float4*)&xb[(size_t)(t+1)*DIM + dd];
        float4 xv2 = *(const float4*)&xb[(size_t)(t+2)*DIM + dd];
        float4 xv3 = *(const float4*)&xb[(size_t)(t+3)*DIM + dd];
#pragma unroll
        for (int i = 0; i < 8; i++) {
            float4 av = *(const float4*)&ab[i*NTOK + t];   // uniform-address broadcast
            acc[i][0] += av.x*xv0.x + av.y*xv1.x + av.z*xv2.x + av.w*xv3.x;
            acc[i][1] += av.x*xv0.y + av.y*xv1.y + av.z*xv2.y + av.w*xv3.y;
            acc[i][2] += av.x*xv0.z + av.y*xv1.z + av.z*xv2.z + av.w*xv3.z;
            acc[i][3] += av.x*xv0.w + av.y*xv1.w + av.z*xv2.w + av.w*xv3.w;
        }
    }
#pragma unroll
    for (int i = 0; i < 8; i++)
        *(float4*)&red[(w*NSLOT + i)*128 + lane*4] =
            make_float4(acc[i][0], acc[i][1], acc[i][2], acc[i][3]);
    __syncthreads();

    // final reduce over 8 token-groups: 1024 outputs, 4 per thread
    for (int o = tid; o < NSLOT*128; o += 256) {
        int i = o >> 7, dl = o & 127;
        float sum = 0.f;
#pragma unroll
        for (int g = 0; g < 8; g++) sum += red[(g*NSLOT + i)*128 + dl];
        g_upd[((size_t)(b*NSLOT) + i)*DIM + half*128 + dl] = sum / rssm[i];
    }
}

// -------- generic C = A @ W^T (+bias) GEMM, 64x64x16 tiles ------------------
// mode bit0: relu, bit1: accumulate into existing C. blockIdx.z picks problem.
__global__ void __launch_bounds__(256) gemm_kernel(
    const float* __restrict__ A0, const float* __restrict__ W0,
    const float* __restrict__ bias0, float* __restrict__ C0,
    const float* __restrict__ A1, const float* __restrict__ W1,
    const float* __restrict__ bias1, float* __restrict__ C1,
    int M, int N, int K, int mode)
{
    const float* A = A0; const float* W = W0; const float* bias = bias0; float* C = C0;
    if (blockIdx.z) { A = A1; W = W1; bias = bias1; C = C1; }
    __shared__ float As[16][68];
    __shared__ float Bs[16][68];
    int tid = threadIdx.x;
    int m0 = blockIdx.y * 64, n0 = blockIdx.x * 64;
    int tx = tid & 15, ty = tid >> 4;
    int lr = tid >> 2, lk = (tid & 3) * 4;
    float acc[4][4] = {};
    for (int k0 = 0; k0 < K; k0 += 16) {
        float4 av = *(const float4*)&A[(size_t)(m0 + lr)*K + k0 + lk];
        float4 wv = *(const float4*)&W[(size_t)(n0 + lr)*K + k0 + lk];
        __syncthreads();
        As[lk+0][lr]=av.x; As[lk+1][lr]=av.y; As[lk+2][lr]=av.z; As[lk+3][lr]=av.w;
        Bs[lk+0][lr]=wv.x; Bs[lk+1][lr]=wv.y; Bs[lk+2][lr]=wv.z; Bs[lk+3][lr]=wv.w;
        __syncthreads();
#pragma unroll
        for (int kk = 0; kk < 16; kk++) {
            float4 a4 = *(const float4*)&As[kk][ty*4];
            float4 b4 = *(const float4*)&Bs[kk][tx*4];
            float a[4]  = {a4.x, a4.y, a4.z, a4.w};
            float bb[4] = {b4.x, b4.y, b4.z, b4.w};
#pragma unroll
            for (int i = 0; i < 4; i++)
#pragma unroll
                for (int j = 0; j < 4; j++) acc[i][j] += a[i] * bb[j];
        }
    }
    float bj[4];
#pragma unroll
    for (int j = 0; j < 4; j++) bj[j] = bias ? bias[n0 + tx*4 + j] : 0.f;
#pragma unroll
    for (int i = 0; i < 4; i++) {
        float* cp = C + (size_t)(m0 + ty*4 + i)*N + n0 + tx*4;
#pragma unroll
        for (int j = 0; j < 4; j++) {
            float v = acc[i][j] + bj[j];
            if (mode & 1) v = fmaxf(v, 0.f);
            if (mode & 2) v += cp[j];
            cp[j] = v;
        }
    }
}

// -------- GRU gates + LN_ff in one pass (1 block per slot row) --------------
__global__ void __launch_bounds__(256) gru_gates_ln_kernel(const float* __restrict__ lw,
                                                           const float* __restrict__ lb) {
    int row = blockIdx.x, d = threadIdx.x, lane = d & 31, w = d >> 5;
    const float* gi = g_gi + (size_t)row * 3*DIM;
    const float* gh = g_gh + (size_t)row * 3*DIM;
    float h = g_slots[(size_t)row*DIM + d];
    float r = 1.f / (1.f + expf(-(gi[d]       + gh[d])));
    float z = 1.f / (1.f + expf(-(gi[DIM+d]   + gh[DIM+d])));
    float n = tanhf(gi[2*DIM+d] + r * gh[2*DIM+d]);
    float s = (1.f - z) * n + z * h;
    g_slots[(size_t)row*DIM + d] = s;

    __shared__ float red[16];
    float ps = warp_sum(s), pq = warp_sum(s*s);
    if (lane == 0) { red[w] = ps; red[8+w] = pq; }
    __syncthreads();
    float tot = 0.f, totq = 0.f;
#pragma unroll
    for (int u = 0; u < 8; u++) { tot += red[u]; totq += red[8+u]; }
    float mu  = tot * (1.f/256.f);
    float var = totq * (1.f/256.f) - mu*mu;
    float rstd = rsqrtf(fmaxf(var, 0.f) + 1e-5f);
    g_sln[(size_t)row*DIM + d] = (s - mu) * rstd * lw[d] + lb[d];
}

__global__ void copy_slots_kernel(float* __restrict__ out) {
    int i = blockIdx.x * 256 + threadIdx.x;
    out[i] = g_slots[i];
}

// ---------------------------------------------------------------------------
extern "C" void kernel_launch(void* const* d_in, const int* in_sizes, int n_in,
                              void* d_out, int out_size) {
    const float* inputs  = (const float*)d_in[0];
    const float* noise   = (const float*)d_in[1];
    const float* mu      = (const float*)d_in[2];
    const float* sigma   = (const float*)d_in[3];
    const float* Wq      = (const float*)d_in[4];
    const float* Wk      = (const float*)d_in[5];
    const float* Wv      = (const float*)d_in[6];
    const float* wih     = (const float*)d_in[7];
    const float* whh     = (const float*)d_in[8];
    const float* bih     = (const float*)d_in[9];
    const float* bhh     = (const float*)d_in[10];
    const float* w1      = (const float*)d_in[11];
    const float* b1      = (const float*)d_in[12];
    const float* w2      = (const float*)d_in[13];
    const float* b2      = (const float*)d_in[14];
    const float* ln_in_w = (const float*)d_in[15];
    const float* ln_in_b = (const float*)d_in[16];
    const float* ln_s_w  = (const float*)d_in[17];
    const float* ln_s_b  = (const float*)d_in[18];
    const float* ln_ff_w = (const float*)d_in[19];
    const float* ln_ff_b = (const float*)d_in[20];

    float* out      = (float*)d_out;
    float* attn_out = out + BATCH*NSLOT*DIM;   // slots first, then attns [b,iter,slot,tok]

    float *p_upd, *p_wuv, *p_slots, *p_gi, *p_gh, *p_sln, *p_h1;
    cudaGetSymbolAddress((void**)&p_upd,   g_upd);
    cudaGetSymbolAddress((void**)&p_wuv,   g_wuv);
    cudaGetSymbolAddress((void**)&p_slots, g_slots);
    cudaGetSymbolAddress((void**)&p_gi,    g_gi);
    cudaGetSymbolAddress((void**)&p_gh,    g_gh);
    cudaGetSymbolAddress((void**)&p_sln,   g_sln);
    cudaGetSymbolAddress((void**)&p_h1,    g_h1);

    slots_init_kernel<<<ROWS, 256>>>(noise, mu, sigma);
    wqk_kernel<<<DIM/8, 256>>>(Wq, Wk);
    wuv_kernel<<<(3*DIM)/8, 256>>>(wih, Wv);
    ln_in_kernel<<<(BATCH*NTOK)/8, 256>>>(inputs, ln_in_w, ln_in_b);

    for (int it = 0; it < NITER; it++) {
        slots_qw_kernel<<<BATCH, 256>>>(ln_s_w, ln_s_b);
        attn_dots_kernel<<<dim3(4, BATCH), 256>>>(attn_out, it);
        attn_y_kernel<<<dim3(2, BATCH), 256>>>(attn_out, it);
        // gi = U' @ W_uv^T + bih ; gh = slots @ whh^T + bhh   (z picks problem)
        gemm_kernel<<<dim3((3*DIM)/64, ROWS/64, 2), 256>>>(
            p_upd, p_wuv, bih, p_gi,
            p_slots, whh, bhh, p_gh,
            ROWS, 3*DIM, DIM, 0);
        gru_gates_ln_kernel<<<ROWS, 256>>>(ln_ff_w, ln_ff_b);
        // h1 = relu(sln @ w1^T + b1)
        gemm_kernel<<<dim3(HID/64, ROWS/64, 1), 256>>>(
            p_sln, w1, b1, p_h1, p_sln, w1, b1, p_h1,
            ROWS, HID, DIM, 1);
        // slots += h1 @ w2^T + b2
        gemm_kernel<<<dim3(DIM/64, ROWS/64, 1), 256>>>(
            p_h1, w2, b2, p_slots, p_h1, w2, b2, p_slots,
            ROWS, DIM, HID, 2);
    }
    copy_slots_kernel<<<ROWS, 256>>>(out);
}

// round 5
// speedup vs baseline: 1.3690x; 1.3136x over previous
#include <cuda_runtime.h>
#include <math.h>

#define BATCH 64
#define NTOK  1024
#define DIM   256
#define NSLOT 8
#define HID   512
#define NITER 3
#define ROWS  (BATCH*NSLOT)   /* 512 */
#define NT4   4               /* 256-token tiles per batch in attn */

// ---------------- scratch (device globals; no allocations allowed) ----------
__device__ float g_xn[BATCH*NTOK*DIM];     // LN(inputs)  64 MB
__device__ float g_slots[ROWS*DIM];
__device__ float g_sln[ROWS*DIM];
__device__ float g_qw[ROWS*DIM];
__device__ float g_wqk[DIM*DIM];           // Wq^T @ Wk
__device__ float g_wuv[3*DIM*DIM];         // gru_wih @ Wv
__device__ float g_upd[ROWS*DIM];
__device__ float g_gi[ROWS*3*DIM];
__device__ float g_gh[ROWS*3*DIM];
__device__ float g_h1[ROWS*HID];
__device__ float g_ypart[BATCH*NT4*NSLOT*DIM];   // 2 MB
__device__ float g_rspart[BATCH*NT4*NSLOT];

__device__ __forceinline__ float warp_sum(float v) {
    v += __shfl_xor_sync(0xffffffffu, v, 16);
    v += __shfl_xor_sync(0xffffffffu, v, 8);
    v += __shfl_xor_sync(0xffffffffu, v, 4);
    v += __shfl_xor_sync(0xffffffffu, v, 2);
    v += __shfl_xor_sync(0xffffffffu, v, 1);
    return v;
}

// ---------------- fused setup: wqk | wuv | slots_init -----------------------
__global__ void __launch_bounds__(256) setup_kernel(
    const float* __restrict__ Wq, const float* __restrict__ Wk,
    const float* __restrict__ wih, const float* __restrict__ Wv,
    const float* __restrict__ noise, const float* __restrict__ mu,
    const float* __restrict__ sigma)
{
    int bid = blockIdx.x, tid = threadIdx.x;
    if (bid < 32) {                       // W_qk[f,d] = sum_e Wq[e,f]*Wk[e,d]
        int f0 = bid * 8, d = tid;
        float acc[8] = {};
        for (int e = 0; e < DIM; e++) {
            float wk = Wk[e*DIM + d];
#pragma unroll
            for (int u = 0; u < 8; u++) acc[u] += Wq[e*DIM + f0 + u] * wk;
        }
#pragma unroll
        for (int u = 0; u < 8; u++) g_wqk[(f0+u)*DIM + d] = acc[u];
    } else if (bid < 128) {               // W_uv[g,e] = sum_d wih[g,d]*Wv[d,e]
        int g0 = (bid - 32) * 8, e = tid;
        float acc[8] = {};
        for (int d = 0; d < DIM; d++) {
            float v = Wv[d*DIM + e];
#pragma unroll
            for (int u = 0; u < 8; u++) acc[u] += wih[(g0+u)*DIM + d] * v;
        }
#pragma unroll
        for (int u = 0; u < 8; u++) g_wuv[(g0+u)*DIM + e] = acc[u];
    } else {                              // slots = mu + noise*exp(sigma)
        int i = (bid - 128) * 256 + tid;
        int d = i & 255;
        g_slots[i] = mu[d] + noise[i] * __expf(sigma[d]);
    }
}

// ---------------- LN(inputs) -> g_xn  (1 warp per row) ----------------------
__global__ void __launch_bounds__(256) ln_in_kernel(const float* __restrict__ in,
                                                    const float* __restrict__ w,
                                                    const float* __restrict__ b) {
    int row  = blockIdx.x * 8 + (threadIdx.x >> 5);
    int lane = threadIdx.x & 31;
    const float4* ip = (const float4*)(in + (size_t)row * DIM);
    float4 v0 = ip[lane*2], v1 = ip[lane*2+1];
    float s  = v0.x+v0.y+v0.z+v0.w + v1.x+v1.y+v1.z+v1.w;
    float sq = v0.x*v0.x+v0.y*v0.y+v0.z*v0.z+v0.w*v0.w
             + v1.x*v1.x+v1.y*v1.y+v1.z*v1.z+v1.w*v1.w;
    s = warp_sum(s); sq = warp_sum(sq);
    float mu  = s * (1.f/256.f);
    float var = sq * (1.f/256.f) - mu*mu;
    float rstd = rsqrtf(fmaxf(var, 0.f) + 1e-5f);
    const float4* wp = (const float4*)w; const float4* bp = (const float4*)b;
    float4 w0 = wp[lane*2], w1 = wp[lane*2+1];
    float4 b0 = bp[lane*2], b1 = bp[lane*2+1];
    float4 o0, o1;
    o0.x=(v0.x-mu)*rstd*w0.x+b0.x; o0.y=(v0.y-mu)*rstd*w0.y+b0.y;
    o0.z=(v0.z-mu)*rstd*w0.z+b0.z; o0.w=(v0.w-mu)*rstd*w0.w+b0.w;
    o1.x=(v1.x-mu)*rstd*w1.x+b1.x; o1.y=(v1.y-mu)*rstd*w1.y+b1.y;
    o1.z=(v1.z-mu)*rstd*w1.z+b1.z; o1.w=(v1.w-mu)*rstd*w1.w+b1.w;
    float4* op = (float4*)(g_xn + (size_t)row * DIM);
    op[lane*2] = o0; op[lane*2+1] = o1;
}

// -------- s = LN_slots(slots); qW = s @ W_qk   (1 block per batch) ----------
__global__ void __launch_bounds__(256) slots_qw_kernel(const float* __restrict__ lw,
                                                       const float* __restrict__ lb) {
    int b = blockIdx.x, tid = threadIdx.x, lane = tid & 31, w = tid >> 5;
    __shared__ float sln[NSLOT*DIM];
    {
        const float4* sp = (const float4*)(g_slots + (size_t)(b*8 + w) * DIM);
        float4 v0 = sp[lane*2], v1 = sp[lane*2+1];
        float s  = v0.x+v0.y+v0.z+v0.w + v1.x+v1.y+v1.z+v1.w;
        float sq = v0.x*v0.x+v0.y*v0.y+v0.z*v0.z+v0.w*v0.w
                 + v1.x*v1.x+v1.y*v1.y+v1.z*v1.z+v1.w*v1.w;
        s = warp_sum(s); sq = warp_sum(sq);
        float mu  = s * (1.f/256.f);
        float var = sq * (1.f/256.f) - mu*mu;
        float rstd = rsqrtf(fmaxf(var, 0.f) + 1e-5f);
        const float4* wp = (const float4*)lw; const float4* bp = (const float4*)lb;
        float4 w0 = wp[lane*2], w1 = wp[lane*2+1];
        float4 b0 = bp[lane*2], b1 = bp[lane*2+1];
        float4 o0, o1;
        o0.x=(v0.x-mu)*rstd*w0.x+b0.x; o0.y=(v0.y-mu)*rstd*w0.y+b0.y;
        o0.z=(v0.z-mu)*rstd*w0.z+b0.z; o0.w=(v0.w-mu)*rstd*w0.w+b0.w;
        o1.x=(v1.x-mu)*rstd*w1.x+b1.x; o1.y=(v1.y-mu)*rstd*w1.y+b1.y;
        o1.z=(v1.z-mu)*rstd*w1.z+b1.z; o1.w=(v1.w-mu)*rstd*w1.w+b1.w;
        float4* op = (float4*)&sln[w*DIM];
        op[lane*2] = o0; op[lane*2+1] = o1;
    }
    __syncthreads();
    float acc[8] = {};
    for (int f = 0; f < DIM; f += 4) {
        float q0 = g_wqk[(f+0)*DIM + tid];
        float q1 = g_wqk[(f+1)*DIM + tid];
        float q2 = g_wqk[(f+2)*DIM + tid];
        float q3 = g_wqk[(f+3)*DIM + tid];
#pragma unroll
        for (int r = 0; r < 8; r++) {
            float4 sv = *(const float4*)&sln[r*DIM + f];
            acc[r] += sv.x*q0 + sv.y*q1 + sv.z*q2 + sv.w*q3;
        }
    }
#pragma unroll
    for (int r = 0; r < 8; r++) g_qw[(size_t)(b*8+r)*DIM + tid] = acc[r];
}

// -------- FUSED attention: dots+softmax+attn-write+rowsum+Y partials --------
// grid (NT4, BATCH), 256 threads, dynamic smem 88 KB:
//   q[8*256] | a[8*256] | red[8 warps][8 slots][256]
__global__ void __launch_bounds__(256) attn_fused_kernel(float* __restrict__ attn_out, int it) {
    extern __shared__ float sm[];
    float* q_sm = sm;                    // 2048
    float* a_sm = sm + 2048;             // 2048
    float* red  = sm + 4096;             // 16384
    int b = blockIdx.y, tile = blockIdx.x;
    int tid = threadIdx.x, lane = tid & 31, w = tid >> 5;
    int j = tile * 256 + tid;

    for (int k = tid; k < NSLOT*DIM; k += 256)
        q_sm[k] = g_qw[(size_t)b*NSLOT*DIM + k] * 0.0625f;
    __syncthreads();

    // ---- phase A: per-thread token dot + softmax over slots ----
    {
        const float4* xp = (const float4*)(g_xn + ((size_t)b*NTOK + j) * DIM);
        const float4* qp = (const float4*)q_sm;
        float s[8] = {};
#pragma unroll 4
        for (int d4 = 0; d4 < 64; d4++) {
            float4 x4 = xp[d4];
#pragma unroll
            for (int i = 0; i < 8; i++) {
                float4 q4 = qp[i*64 + d4];
                s[i] += x4.x*q4.x + x4.y*q4.y + x4.z*q4.z + x4.w*q4.w;
            }
        }
        float m = s[0];
#pragma unroll
        for (int i = 1; i < 8; i++) m = fmaxf(m, s[i]);
        float a[8], asum = 0.f;
#pragma unroll
        for (int i = 0; i < 8; i++) { a[i] = __expf(s[i] - m); asum += a[i]; }
        float inv = 1.f / asum;
        float* ap = attn_out + ((size_t)(b*NITER + it)*NSLOT)*NTOK + j;
#pragma unroll
        for (int i = 0; i < 8; i++) {
            float av = a[i]*inv + 1e-8f;
            ap[i*NTOK] = av;
            a_sm[i*256 + tid] = av;
        }
    }
    __syncthreads();

    // ---- per-tile rowsum: warp w sums slot w ----
    {
        float rs = 0.f;
#pragma unroll
        for (int k = 0; k < 8; k++) rs += a_sm[w*256 + lane + 32*k];
        rs = warp_sum(rs);
        if (lane == 0) g_rspart[(b*NT4 + tile)*NSLOT + w] = rs;
    }

    // ---- phase B: Y[i,d] = sum_j a[i,j]*x[j,d] over this 256-token tile ----
    // warp w: tokens [w*32, w*32+32); lane: dims lane*8..lane*8+7
    {
        const float* xb = g_xn + ((size_t)b*NTOK + tile*256) * DIM;
        int d0 = lane * 8;
        float acc[8][8] = {};
        for (int tt = 0; tt < 32; tt++) {
            int t = w*32 + tt;
            float4 xv0 = *(const float4*)&xb[(size_t)t*DIM + d0];
            float4 xv1 = *(const float4*)&xb[(size_t)t*DIM + d0 + 4];
#pragma unroll
            for (int i = 0; i < 8; i++) {
                float ai = a_sm[i*256 + t];
                acc[i][0] += ai*xv0.x; acc[i][1] += ai*xv0.y;
                acc[i][2] += ai*xv0.z; acc[i][3] += ai*xv0.w;
                acc[i][4] += ai*xv1.x; acc[i][5] += ai*xv1.y;
                acc[i][6] += ai*xv1.z; acc[i][7] += ai*xv1.w;
            }
        }
#pragma unroll
        for (int i = 0; i < 8; i++) {
            *(float4*)&red[(w*NSLOT + i)*256 + d0]     = make_float4(acc[i][0],acc[i][1],acc[i][2],acc[i][3]);
            *(float4*)&red[(w*NSLOT + i)*256 + d0 + 4] = make_float4(acc[i][4],acc[i][5],acc[i][6],acc[i][7]);
        }
    }
    __syncthreads();

    // ---- reduce 8 warps -> ypart ----
    float* yp = g_ypart + (size_t)((b*NT4 + tile)*NSLOT) * DIM;
    for (int o = tid; o < NSLOT*DIM; o += 256) {
        int i = o >> 8, d = o & 255;
        float sum = 0.f;
#pragma unroll
        for (int g = 0; g < 8; g++) sum += red[(g*NSLOT + i)*256 + d];
        yp[o] = sum;
    }
}

// -------- reduce tile partials -> U' ----------------------------------------
__global__ void __launch_bounds__(256) reduce_u_kernel() {
    int row = blockIdx.x, d = threadIdx.x;
    int b = row >> 3, i = row & 7;
    float y = 0.f, rsv = 0.f;
#pragma unroll
    for (int t = 0; t < NT4; t++) {
        y   += g_ypart[(size_t)((b*NT4 + t)*NSLOT + i)*DIM + d];
        rsv += g_rspart[(b*NT4 + t)*NSLOT + i];
    }
    g_upd[(size_t)row*DIM + d] = y / rsv;
}

// -------- GEMM 64x64x16, two-problem, C = A @ W^T (+bias) -------------------
__global__ void __launch_bounds__(256) gemm_kernel(
    const float* __restrict__ A0, const float* __restrict__ W0,
    const float* __restrict__ bias0, float* __restrict__ C0,
    const float* __restrict__ A1, const float* __restrict__ W1,
    const float* __restrict__ bias1, float* __restrict__ C1,
    int M, int N, int K, int mode)
{
    const float* A = A0; const float* W = W0; const float* bias = bias0; float* C = C0;
    if (blockIdx.z) { A = A1; W = W1; bias = bias1; C = C1; }
    __shared__ float As[16][68];
    __shared__ float Bs[16][68];
    int tid = threadIdx.x;
    int m0 = blockIdx.y * 64, n0 = blockIdx.x * 64;
    int tx = tid & 15, ty = tid >> 4;
    int lr = tid >> 2, lk = (tid & 3) * 4;
    float acc[4][4] = {};
    for (int k0 = 0; k0 < K; k0 += 16) {
        float4 av = *(const float4*)&A[(size_t)(m0 + lr)*K + k0 + lk];
        float4 wv = *(const float4*)&W[(size_t)(n0 + lr)*K + k0 + lk];
        __syncthreads();
        As[lk+0][lr]=av.x; As[lk+1][lr]=av.y; As[lk+2][lr]=av.z; As[lk+3][lr]=av.w;
        Bs[lk+0][lr]=wv.x; Bs[lk+1][lr]=wv.y; Bs[lk+2][lr]=wv.z; Bs[lk+3][lr]=wv.w;
        __syncthreads();
#pragma unroll
        for (int kk = 0; kk < 16; kk++) {
            float4 a4 = *(const float4*)&As[kk][ty*4];
            float4 b4 = *(const float4*)&Bs[kk][tx*4];
            float a[4]  = {a4.x, a4.y, a4.z, a4.w};
            float bb[4] = {b4.x, b4.y, b4.z, b4.w};
#pragma unroll
            for (int i = 0; i < 4; i++)
#pragma unroll
                for (int jx = 0; jx < 4; jx++) acc[i][jx] += a[i] * bb[jx];
        }
    }
    float bj[4];
#pragma unroll
    for (int jx = 0; jx < 4; jx++) bj[jx] = bias ? bias[n0 + tx*4 + jx] : 0.f;
#pragma unroll
    for (int i = 0; i < 4; i++) {
        float* cp = C + (size_t)(m0 + ty*4 + i)*N + n0 + tx*4;
#pragma unroll
        for (int jx = 0; jx < 4; jx++) {
            float v = acc[i][jx] + bj[jx];
            if (mode & 1) v = fmaxf(v, 0.f);
            if (mode & 2) v += cp[jx];
            cp[jx] = v;
        }
    }
}

// -------- GEMM 32x64x16 single-problem (higher occupancy for small GEMMs) ---
// mode bit0 relu, bit1 accumulate into C, bit2 mirror final value to C2
__global__ void __launch_bounds__(256) gemm32_kernel(
    const float* __restrict__ A, const float* __restrict__ W,
    const float* __restrict__ bias, float* __restrict__ C,
    float* __restrict__ C2, int M, int N, int K, int mode)
{
    __shared__ float As[16][36];
    __shared__ float Bs[16][68];
    int tid = threadIdx.x;
    int m0 = blockIdx.y * 32, n0 = blockIdx.x * 64;
    int tx = tid & 15, ty = tid >> 4;            // ty 0..15 -> 2 rows, tx -> 4 cols
    int lr = tid >> 2, lk = (tid & 3) * 4;       // B loader: 64 rows
    float acc[2][4] = {};
    for (int k0 = 0; k0 < K; k0 += 16) {
        float4 av = make_float4(0.f,0.f,0.f,0.f);
        if (tid < 128) av = *(const float4*)&A[(size_t)(m0 + (tid>>2))*K + k0 + lk];
        float4 wv = *(const float4*)&W[(size_t)(n0 + lr)*K + k0 + lk];
        __syncthreads();
        if (tid < 128) {
            int ar = tid >> 2;
            As[lk+0][ar]=av.x; As[lk+1][ar]=av.y; As[lk+2][ar]=av.z; As[lk+3][ar]=av.w;
        }
        Bs[lk+0][lr]=wv.x; Bs[lk+1][lr]=wv.y; Bs[lk+2][lr]=wv.z; Bs[lk+3][lr]=wv.w;
        __syncthreads();
#pragma unroll
        for (int kk = 0; kk < 16; kk++) {
            float a0 = As[kk][ty*2], a1 = As[kk][ty*2+1];
            float4 b4 = *(const float4*)&Bs[kk][tx*4];
            acc[0][0] += a0*b4.x; acc[0][1] += a0*b4.y; acc[0][2] += a0*b4.z; acc[0][3] += a0*b4.w;
            acc[1][0] += a1*b4.x; acc[1][1] += a1*b4.y; acc[1][2] += a1*b4.z; acc[1][3] += a1*b4.w;
        }
    }
    float bj[4];
#pragma unroll
    for (int jx = 0; jx < 4; jx++) bj[jx] = bias ? bias[n0 + tx*4 + jx] : 0.f;
#pragma unroll
    for (int i = 0; i < 2; i++) {
        size_t off = (size_t)(m0 + ty*2 + i)*N + n0 + tx*4;
        float* cp = C + off;
#pragma unroll
        for (int jx = 0; jx < 4; jx++) {
            float v = acc[i][jx] + bj[jx];
            if (mode & 1) v = fmaxf(v, 0.f);
            if (mode & 2) v += cp[jx];
            cp[jx] = v;
            if (mode & 4) C2[off + jx] = v;
        }
    }
}

// -------- GRU gates + LN_ff in one pass (1 block per slot row) --------------
__global__ void __launch_bounds__(256) gru_gates_ln_kernel(const float* __restrict__ lw,
                                                           const float* __restrict__ lb) {
    int row = blockIdx.x, d = threadIdx.x, lane = d & 31, w = d >> 5;
    const float* gi = g_gi + (size_t)row * 3*DIM;
    const float* gh = g_gh + (size_t)row * 3*DIM;
    float h = g_slots[(size_t)row*DIM + d];
    float r = 1.f / (1.f + __expf(-(gi[d]     + gh[d])));
    float z = 1.f / (1.f + __expf(-(gi[DIM+d] + gh[DIM+d])));
    float nx = gi[2*DIM+d] + r * gh[2*DIM+d];
    nx = fminf(fmaxf(nx, -15.f), 15.f);
    float e2 = __expf(2.f*nx);
    float n = (e2 - 1.f) / (e2 + 1.f);
    float s = (1.f - z) * n + z * h;
    g_slots[(size_t)row*DIM + d] = s;

    __shared__ float red[16];
    float ps = warp_sum(s), pq = warp_sum(s*s);
    if (lane == 0) { red[w] = ps; red[8+w] = pq; }
    __syncthreads();
    float tot = 0.f, totq = 0.f;
#pragma unroll
    for (int u = 0; u < 8; u++) { tot += red[u]; totq += red[8+u]; }
    float mu  = tot * (1.f/256.f);
    float var = totq * (1.f/256.f) - mu*mu;
    float rstd = rsqrtf(fmaxf(var, 0.f) + 1e-5f);
    g_sln[(size_t)row*DIM + d] = (s - mu) * rstd * lw[d] + lb[d];
}

// ---------------------------------------------------------------------------
extern "C" void kernel_launch(void* const* d_in, const int* in_sizes, int n_in,
                              void* d_out, int out_size) {
    const float* inputs  = (const float*)d_in[0];
    const float* noise   = (const float*)d_in[1];
    const float* mu      = (const float*)d_in[2];
    const float* sigma   = (const float*)d_in[3];
    const float* Wq      = (const float*)d_in[4];
    const float* Wk      = (const float*)d_in[5];
    const float* Wv      = (const float*)d_in[6];
    const float* wih     = (const float*)d_in[7];
    const float* whh     = (const float*)d_in[8];
    const float* bih     = (const float*)d_in[9];
    const float* bhh     = (const float*)d_in[10];
    const float* w1      = (const float*)d_in[11];
    const float* b1      = (const float*)d_in[12];
    const float* w2      = (const float*)d_in[13];
    const float* b2      = (const float*)d_in[14];
    const float* ln_in_w = (const float*)d_in[15];
    const float* ln_in_b = (const float*)d_in[16];
    const float* ln_s_w  = (const float*)d_in[17];
    const float* ln_s_b  = (const float*)d_in[18];
    const float* ln_ff_w = (const float*)d_in[19];
    const float* ln_ff_b = (const float*)d_in[20];

    float* out      = (float*)d_out;
    float* attn_out = out + BATCH*NSLOT*DIM;   // slots first, then attns

    float *p_upd, *p_wuv, *p_slots, *p_gi, *p_gh, *p_sln, *p_h1;
    cudaGetSymbolAddress((void**)&p_upd,   g_upd);
    cudaGetSymbolAddress((void**)&p_wuv,   g_wuv);
    cudaGetSymbolAddress((void**)&p_slots, g_slots);
    cudaGetSymbolAddress((void**)&p_gi,    g_gi);
    cudaGetSymbolAddress((void**)&p_gh,    g_gh);
    cudaGetSymbolAddress((void**)&p_sln,   g_sln);
    cudaGetSymbolAddress((void**)&p_h1,    g_h1);

    static const int ATTN_SMEM = (2048 + 2048 + 16384) * 4;   // 88 KB
    cudaFuncSetAttribute(attn_fused_kernel,
                         cudaFuncAttributeMaxDynamicSharedMemorySize, ATTN_SMEM);

    // order chosen so ncu's skip-5 window lands on attn_fused (iter 0)
    ln_in_kernel<<<(BATCH*NTOK)/8, 256>>>(inputs, ln_in_w, ln_in_b);
    setup_kernel<<<128 + ROWS, 256>>>(Wq, Wk, wih, Wv, noise, mu, sigma);

    for (int it = 0; it < NITER; it++) {
        slots_qw_kernel<<<BATCH, 256>>>(ln_s_w, ln_s_b);
        attn_fused_kernel<<<dim3(NT4, BATCH), 256, ATTN_SMEM>>>(attn_out, it);
        reduce_u_kernel<<<ROWS, 256>>>();
        // gi = U' @ W_uv^T + bih ; gh = slots @ whh^T + bhh
        gemm_kernel<<<dim3((3*DIM)/64, ROWS/64, 2), 256>>>(
            p_upd, p_wuv, bih, p_gi,
            p_slots, whh, bhh, p_gh,
            ROWS, 3*DIM, DIM, 0);
        gru_gates_ln_kernel<<<ROWS, 256>>>(ln_ff_w, ln_ff_b);
        // h1 = relu(sln @ w1^T + b1)
        gemm32_kernel<<<dim3(HID/64, ROWS/32), 256>>>(
            p_sln, w1, b1, p_h1, p_h1, ROWS, HID, DIM, 1);
        // slots += h1 @ w2^T + b2 ; final iter also writes slots to out
        int mode = 2 | ((it == NITER-1) ? 4 : 0);
        gemm32_kernel<<<dim3(DIM/64, ROWS/32), 256>>>(
            p_h1, w2, b2, p_slots, out, ROWS, DIM, HID, mode);
    }
}